// round 12
// baseline (speedup 1.0000x reference)
#include <cuda_runtime.h>
#include <cstdint>

#define BB   2
#define TT   2048
#define DD   1024
#define HH   16
#define HDIM 64
#define MM   (BB*TT)          // 4096
#define NQ   (HH*HDIM)        // 1024
#define SZ   (BB*HH*TT*HDIM)  // 4,194,304

// One scratch array: [0]=q, [1]=k, [2]=v, [3]=attention output
__device__ __align__(256) float g_scratch[4ull * SZ];

// ======================= mma.sync tf32 helpers =============================
__device__ __forceinline__ void mma_tf32(float* d, const uint32_t* a,
                                         const uint32_t* b) {
    asm volatile(
        "mma.sync.aligned.m16n8k8.row.col.f32.tf32.tf32.f32 "
        "{%0,%1,%2,%3}, {%4,%5,%6,%7}, {%8,%9}, {%0,%1,%2,%3};"
        : "+f"(d[0]), "+f"(d[1]), "+f"(d[2]), "+f"(d[3])
        : "r"(a[0]), "r"(a[1]), "r"(a[2]), "r"(a[3]), "r"(b[0]), "r"(b[1]));
}
__device__ __forceinline__ float hi_part(float x) {
    return __uint_as_float(__float_as_uint(x) & 0xFFFFE000u);
}

// =================== GEMM smem layout (interleaved hi/lo) ==================
// A: [ks(2)][row(128)][pos(16)]  pos = tg*4 + half*2 + hl   plane pad 2064
// B: [n(128)][pos(32)^swz]       pos = (ks*16 + tg*4)^(swz<<2) + half*2+hl
#define APLANE 2064
#define BROW   48
struct GemmSmem {
    float A[2 * APLANE];     // 16.5 KB
    float B[128 * BROW];     // 24 KB
};

__device__ __forceinline__ void mma_chunk(const float* __restrict__ As,
                                          const float* __restrict__ Bs,
                                          int wid, int lane,
                                          float acc[4][4][4]) {
    const int warp_m = (wid >> 2) * 64;
    const int warp_n = (wid & 3) * 32;
    const int g  = lane >> 2;
    const int tg = lane & 3;
#pragma unroll
    for (int ks = 0; ks < 2; ks++) {
        uint32_t ah[4][4], al[4][4];
#pragma unroll
        for (int mt = 0; mt < 4; mt++) {
            const int r0 = warp_m + mt * 16 + g;
            float4 f0 = *reinterpret_cast<const float4*>(
                &As[ks * APLANE + r0 * 16 + tg * 4]);
            float4 f1 = *reinterpret_cast<const float4*>(
                &As[ks * APLANE + (r0 + 8) * 16 + tg * 4]);
            ah[mt][0] = __float_as_uint(f0.x); al[mt][0] = __float_as_uint(f0.y);
            ah[mt][2] = __float_as_uint(f0.z); al[mt][2] = __float_as_uint(f0.w);
            ah[mt][1] = __float_as_uint(f1.x); al[mt][1] = __float_as_uint(f1.y);
            ah[mt][3] = __float_as_uint(f1.z); al[mt][3] = __float_as_uint(f1.w);
        }
#pragma unroll
        for (int nt = 0; nt < 4; nt++) {
            const int n0  = warp_n + nt * 8 + g;
            const int swz = (n0 >> 2) & 7;
            float4 fb = *reinterpret_cast<const float4*>(
                &Bs[n0 * BROW + ((ks * 16 + tg * 4) ^ (swz << 2))]);
            uint32_t bh[2] = {__float_as_uint(fb.x), __float_as_uint(fb.z)};
            uint32_t bl[2] = {__float_as_uint(fb.y), __float_as_uint(fb.w)};
#pragma unroll
            for (int mt = 0; mt < 4; mt++) {
                mma_tf32(acc[mt][nt], ah[mt], bh);
                mma_tf32(acc[mt][nt], ah[mt], bl);
                mma_tf32(acc[mt][nt], al[mt], bh);
            }
        }
    }
}

// store one global float4 of A (row, k=ac4..ac4+3) into interleaved smem
__device__ __forceinline__ void store_a4(float* As, int row, int ac4, float4 av) {
    const int ks = ac4 >> 3, half = (ac4 >> 2) & 1;
    float* base = &As[ks * APLANE + row * 16 + half * 2];
    const float v[4] = {av.x, av.y, av.z, av.w};
#pragma unroll
    for (int u = 0; u < 4; u++) {
        float hv = hi_part(v[u]);
        *reinterpret_cast<float2*>(base + u * 4) = make_float2(hv, v[u] - hv);
    }
}
// store one global float4 of B (k fixed, n=bn4..bn4+3)
__device__ __forceinline__ void store_b4(float* Bs, int k, int bn4, float4 bv) {
    const int ks = k >> 3, tgk = k & 3, hb = (k >> 2) & 1;
    const int swz = (bn4 >> 2) & 7;
    const int pos = (((ks * 16 + tgk * 4) ^ (swz << 2))) + hb * 2;
    const float w[4] = {bv.x, bv.y, bv.z, bv.w};
#pragma unroll
    for (int j = 0; j < 4; j++) {
        float hv = hi_part(w[j]);
        *reinterpret_cast<float2*>(&Bs[(bn4 + j) * BROW + pos]) =
            make_float2(hv, w[j] - hv);
    }
}

// ---------------------------------------------------------------------------
// QKV projection (tensor). Grid (32, 8, 3), block 256, 2 CTAs/SM.
// ---------------------------------------------------------------------------
__global__ __launch_bounds__(256, 2)
void qkv_mma_kernel(const float* __restrict__ x,
                    const float* __restrict__ Wq,
                    const float* __restrict__ Wk,
                    const float* __restrict__ Wv) {
    __shared__ GemmSmem sm;
    const float* W = (blockIdx.z == 0) ? Wq : (blockIdx.z == 1) ? Wk : Wv;
    float* out = g_scratch + (size_t)blockIdx.z * SZ;

    const int bm   = blockIdx.x * 128;
    const int bn   = blockIdx.y * 128;
    const int tid  = threadIdx.x;
    const int wid  = tid >> 5;
    const int lane = tid & 31;

    float acc[4][4][4];
#pragma unroll
    for (int mt = 0; mt < 4; mt++)
#pragma unroll
        for (int nt = 0; nt < 4; nt++)
#pragma unroll
            for (int r = 0; r < 4; r++) acc[mt][nt][r] = 0.f;

    for (int c = 0; c < 64; c++) {
        const int k0 = c * 16;
        float4 av[2], bv[2];
        int arow[2], ac4[2], bkk[2], bn4[2];
#pragma unroll
        for (int it = 0; it < 2; it++) {
            int idx = tid + it * 256;
            arow[it] = idx >> 2;
            ac4[it]  = (idx & 3) << 2;
            av[it] = *reinterpret_cast<const float4*>(
                &x[(size_t)(bm + arow[it]) * DD + k0 + ac4[it]]);
            bkk[it] = idx >> 5;
            bn4[it] = (idx & 31) << 2;
            int n = bn + bn4[it];
            bv[it] = *reinterpret_cast<const float4*>(
                &W[((size_t)(n >> 6) * DD + (k0 + bkk[it])) * HDIM + (n & 63)]);
        }
        if (c > 0) __syncthreads();
#pragma unroll
        for (int it = 0; it < 2; it++) {
            store_a4(sm.A, arow[it], ac4[it], av[it]);
            store_b4(sm.B, bkk[it], bn4[it], bv[it]);
        }
        __syncthreads();
        mma_chunk(sm.A, sm.B, wid, lane, acc);
    }

    const int warp_m = (wid >> 2) * 64;
    const int warp_n = (wid & 3) * 32;
    const int g  = lane >> 2;
    const int tg = lane & 3;
#pragma unroll
    for (int mt = 0; mt < 4; mt++) {
#pragma unroll
        for (int nt = 0; nt < 4; nt++) {
#pragma unroll
            for (int r = 0; r < 4; r++) {
                int m = bm + warp_m + mt * 16 + g + ((r >= 2) ? 8 : 0);
                int n = bn + warp_n + nt * 8 + tg * 2 + (r & 1);
                int b = m >> 11, t = m & 2047;
                out[(((size_t)b * HH + (n >> 6)) * TT + t) * HDIM + (n & 63)] =
                    acc[mt][nt][r];
            }
        }
    }
}

// ---------------------------------------------------------------------------
// Output projection (tensor). Grid (32, 8), block 256, 2 CTAs/SM.
// ---------------------------------------------------------------------------
__global__ __launch_bounds__(256, 2)
void out_mma_kernel(const float* __restrict__ Wo,
                    const float* __restrict__ bo,
                    float* __restrict__ outp) {
    __shared__ GemmSmem sm;
    const float* A = g_scratch + 3ull * SZ;

    const int bm   = blockIdx.x * 128;
    const int bn   = blockIdx.y * 128;
    const int tid  = threadIdx.x;
    const int wid  = tid >> 5;
    const int lane = tid & 31;

    float acc[4][4][4];
#pragma unroll
    for (int mt = 0; mt < 4; mt++)
#pragma unroll
        for (int nt = 0; nt < 4; nt++)
#pragma unroll
            for (int r = 0; r < 4; r++) acc[mt][nt][r] = 0.f;

    for (int c = 0; c < 64; c++) {
        const int k0 = c * 16;
        float4 av[2], bv[2];
        int arow[2], ac4[2], bkk[2], bn4[2];
#pragma unroll
        for (int it = 0; it < 2; it++) {
            int idx = tid + it * 256;
            arow[it] = idx >> 2;
            ac4[it]  = (idx & 3) << 2;
            av[it] = *reinterpret_cast<const float4*>(
                &A[(size_t)(bm + arow[it]) * DD + k0 + ac4[it]]);
            bkk[it] = idx >> 5;
            bn4[it] = (idx & 31) << 2;
            bv[it] = *reinterpret_cast<const float4*>(
                &Wo[(size_t)(k0 + bkk[it]) * DD + bn + bn4[it]]);
        }
        if (c > 0) __syncthreads();
#pragma unroll
        for (int it = 0; it < 2; it++) {
            store_a4(sm.A, arow[it], ac4[it], av[it]);
            store_b4(sm.B, bkk[it], bn4[it], bv[it]);
        }
        __syncthreads();
        mma_chunk(sm.A, sm.B, wid, lane, acc);
    }

    const int warp_m = (wid >> 2) * 64;
    const int warp_n = (wid & 3) * 32;
    const int g  = lane >> 2;
    const int tg = lane & 3;
#pragma unroll
    for (int mt = 0; mt < 4; mt++) {
#pragma unroll
        for (int nt = 0; nt < 4; nt++) {
#pragma unroll
            for (int r = 0; r < 4; r++) {
                int m = bm + warp_m + mt * 16 + g + ((r >= 2) ? 8 : 0);
                int n = bn + warp_n + nt * 8 + tg * 2 + (r & 1);
                outp[(size_t)m * DD + n] = acc[mt][nt][r] + bo[n];
            }
        }
    }
}

// ---------------------------------------------------------------------------
// Tensor-core flash attention (causal), split-tf32, online softmax.
// Grid: (B*H, T/64). Block: 128 threads = 4 warps; warp owns 16 query rows.
// K: interleaved hi/lo layout [key][144] w/ swizzle; P: [row][80] interleaved
// (unioned with K); V: hi/lo arrays, scalar frag loads (unchanged from R10).
// ---------------------------------------------------------------------------
#define KSTR2 144
#define PSTR2 80
#define VSTR  72

__global__ __launch_bounds__(128)
void attn_mma_kernel() {
    __shared__ float sU[64 * PSTR2];   // 5120 words: K(32*144=4608) union P(5120)
    __shared__ float sVh[32 * VSTR];
    __shared__ float sVl[32 * VSTR];
    float* Ksm = sU;
    float* Pu  = sU;

    const int bh = blockIdx.x;          // b*H + h
    const int qt = blockIdx.y;          // 64-query tile
    const int bb = bh >> 4;
    const int h  = bh & 15;
    const size_t base = (size_t)bh * TT * HDIM;
    const float* Qg = g_scratch + 0ull * SZ + base;
    const float* Kg = g_scratch + 1ull * SZ + base;
    const float* Vg = g_scratch + 2ull * SZ + base;
    float*       Og = g_scratch + 3ull * SZ;

    const int tid  = threadIdx.x;
    const int wid  = tid >> 5;
    const int lane = tid & 31;
    const int g    = lane >> 2;
    const int tg   = lane & 3;
    const int wr   = wid * 16;
    const int qrow0 = qt * 64 + wr + g;
    const int qrow1 = qrow0 + 8;

    // ---- load Q fragments (pre-split hi/lo) ----
    uint32_t qh[8][4], ql[8][4];
#pragma unroll
    for (int ks = 0; ks < 8; ks++) {
        const int kb = ks * 8;
#pragma unroll
        for (int r = 0; r < 4; r++) {
            int row = (r & 1) ? qrow1 : qrow0;
            int col = kb + tg + ((r >= 2) ? 4 : 0);
            float v = __ldg(&Qg[(size_t)row * HDIM + col]);
            float hv = hi_part(v);
            qh[ks][r] = __float_as_uint(hv);
            ql[ks][r] = __float_as_uint(v - hv);
        }
    }

    float oacc[8][4];
#pragma unroll
    for (int nt = 0; nt < 8; nt++)
#pragma unroll
        for (int r = 0; r < 4; r++) oacc[nt][r] = 0.f;
    float mrow0 = -1e30f, mrow1 = -1e30f, lrow0 = 0.f, lrow1 = 0.f;
    const float scale = 0.125f;

    const int kt_max = 2 * qt + 1;
    for (int kt = 0; kt <= kt_max; kt++) {
        __syncthreads();   // prev iter's P/V reads done before overwrite
        // ---- load K (interleaved+swizzled) and V (hi/lo) tiles ----
#pragma unroll
        for (int it = 0; it < 4; it++) {
            int idx = tid + it * 128;            // 0..511 float4 slots
            int row = idx >> 4, c4 = (idx & 15) << 2;
            float4 kv = *reinterpret_cast<const float4*>(
                &Kg[(size_t)(kt * 32 + row) * HDIM + c4]);
            {
                const int ksd = c4 >> 3, half = (c4 >> 2) & 1;
                const int swz = (ksd >> 1) & 3;
                float* kb_ = &Ksm[row * KSTR2 + ksd * 16 + half * 2];
                const float v[4] = {kv.x, kv.y, kv.z, kv.w};
#pragma unroll
                for (int u = 0; u < 4; u++) {
                    float hv = hi_part(v[u]);
                    *reinterpret_cast<float2*>(kb_ + ((u ^ swz) << 2)) =
                        make_float2(hv, v[u] - hv);
                }
            }
            float4 vv = *reinterpret_cast<const float4*>(
                &Vg[(size_t)(kt * 32 + row) * HDIM + c4]);
            float4 h4, l4;
            h4.x = hi_part(vv.x); l4.x = vv.x - h4.x;
            h4.y = hi_part(vv.y); l4.y = vv.y - h4.y;
            h4.z = hi_part(vv.z); l4.z = vv.z - h4.z;
            h4.w = hi_part(vv.w); l4.w = vv.w - h4.w;
            *reinterpret_cast<float4*>(&sVh[row * VSTR + c4]) = h4;
            *reinterpret_cast<float4*>(&sVl[row * VSTR + c4]) = l4;
        }
        __syncthreads();

        // ---- S = Q K^T (warp: 16 rows x 32 cols; nt=4) ----
        float sacc[4][4];
#pragma unroll
        for (int nt = 0; nt < 4; nt++)
#pragma unroll
            for (int r = 0; r < 4; r++) sacc[nt][r] = 0.f;
#pragma unroll
        for (int ks = 0; ks < 8; ks++) {
            const int swz = (ks >> 1) & 3;
#pragma unroll
            for (int nt = 0; nt < 4; nt++) {
                const int n0 = nt * 8 + g;
                float4 f = *reinterpret_cast<const float4*>(
                    &Ksm[n0 * KSTR2 + ks * 16 + ((tg ^ swz) << 2)]);
                uint32_t bhf[2] = {__float_as_uint(f.x), __float_as_uint(f.z)};
                uint32_t blf[2] = {__float_as_uint(f.y), __float_as_uint(f.w)};
                mma_tf32(sacc[nt], qh[ks], bhf);
                mma_tf32(sacc[nt], qh[ks], blf);
                mma_tf32(sacc[nt], ql[ks], bhf);
            }
        }

        // ---- scale + causal mask + online softmax ----
        float mt0 = -1e30f, mt1 = -1e30f;
#pragma unroll
        for (int nt = 0; nt < 4; nt++) {
#pragma unroll
            for (int j = 0; j < 2; j++) {
                int scol = kt * 32 + nt * 8 + 2 * tg + j;
                float sv0 = sacc[nt][j] * scale;
                if (scol > qrow0) sv0 = -1e30f;
                sacc[nt][j] = sv0;
                mt0 = fmaxf(mt0, sv0);
                float sv1 = sacc[nt][2 + j] * scale;
                if (scol > qrow1) sv1 = -1e30f;
                sacc[nt][2 + j] = sv1;
                mt1 = fmaxf(mt1, sv1);
            }
        }
        mt0 = fmaxf(mt0, __shfl_xor_sync(0xffffffffu, mt0, 1));
        mt0 = fmaxf(mt0, __shfl_xor_sync(0xffffffffu, mt0, 2));
        mt1 = fmaxf(mt1, __shfl_xor_sync(0xffffffffu, mt1, 1));
        mt1 = fmaxf(mt1, __shfl_xor_sync(0xffffffffu, mt1, 2));

        float mn0 = fmaxf(mrow0, mt0), mn1 = fmaxf(mrow1, mt1);
        float corr0 = __expf(mrow0 - mn0), corr1 = __expf(mrow1 - mn1);
        mrow0 = mn0; mrow1 = mn1;
        float sum0 = 0.f, sum1 = 0.f;
#pragma unroll
        for (int nt = 0; nt < 4; nt++) {
#pragma unroll
            for (int j = 0; j < 2; j++) {
                float p0 = __expf(sacc[nt][j] - mn0);
                sacc[nt][j] = p0; sum0 += p0;
                float p1 = __expf(sacc[nt][2 + j] - mn1);
                sacc[nt][2 + j] = p1; sum1 += p1;
            }
        }
        sum0 += __shfl_xor_sync(0xffffffffu, sum0, 1);
        sum0 += __shfl_xor_sync(0xffffffffu, sum0, 2);
        sum1 += __shfl_xor_sync(0xffffffffu, sum1, 1);
        sum1 += __shfl_xor_sync(0xffffffffu, sum1, 2);
        lrow0 = lrow0 * corr0 + sum0;
        lrow1 = lrow1 * corr1 + sum1;
#pragma unroll
        for (int nt = 0; nt < 8; nt++) {
            oacc[nt][0] *= corr0; oacc[nt][1] *= corr0;
            oacc[nt][2] *= corr1; oacc[nt][3] *= corr1;
        }

        __syncthreads();   // all warps done reading K before P overwrites it

        // ---- write P (interleaved hi/lo, warp-private rows) ----
#pragma unroll
        for (int nt = 0; nt < 4; nt++) {
#pragma unroll
            for (int j = 0; j < 2; j++) {
                const int c8  = 2 * tg + j;
                const int pos = nt * 16 + (c8 & 3) * 4 + (c8 >> 2) * 2;
                float p = sacc[nt][j];
                float hp = hi_part(p);
                *reinterpret_cast<float2*>(&Pu[(wr + g) * PSTR2 + pos]) =
                    make_float2(hp, p - hp);
                p = sacc[nt][2 + j];
                hp = hi_part(p);
                *reinterpret_cast<float2*>(&Pu[(wr + g + 8) * PSTR2 + pos]) =
                    make_float2(hp, p - hp);
            }
        }
        __syncwarp();

        // ---- O += P @ V (warp: 16 rows x 64 cols; nt=8, k=32) ----
#pragma unroll
        for (int ks = 0; ks < 4; ks++) {
            const int kb = ks * 8;
            float4 f0 = *reinterpret_cast<const float4*>(
                &Pu[(wr + g) * PSTR2 + ks * 16 + tg * 4]);
            float4 f1 = *reinterpret_cast<const float4*>(
                &Pu[(wr + g + 8) * PSTR2 + ks * 16 + tg * 4]);
            uint32_t pa[4] = {__float_as_uint(f0.x), __float_as_uint(f1.x),
                              __float_as_uint(f0.z), __float_as_uint(f1.z)};
            uint32_t pb[4] = {__float_as_uint(f0.y), __float_as_uint(f1.y),
                              __float_as_uint(f0.w), __float_as_uint(f1.w)};
#pragma unroll
            for (int nt = 0; nt < 8; nt++) {
                const int n0 = nt * 8 + g;
                uint32_t vh[2], vl[2];
                vh[0] = __float_as_uint(sVh[(kb + tg) * VSTR + n0]);
                vh[1] = __float_as_uint(sVh[(kb + 4 + tg) * VSTR + n0]);
                vl[0] = __float_as_uint(sVl[(kb + tg) * VSTR + n0]);
                vl[1] = __float_as_uint(sVl[(kb + 4 + tg) * VSTR + n0]);
                mma_tf32(oacc[nt], pa, vh);
                mma_tf32(oacc[nt], pa, vl);
                mma_tf32(oacc[nt], pb, vh);
            }
        }
    }

    // ---- epilogue: normalize, write [B,T,H*HD] ----
    const float inv0 = 1.f / lrow0;
    const float inv1 = 1.f / lrow1;
    const size_t ob0 = ((size_t)bb * TT + qrow0) * (HH * HDIM) + h * HDIM;
    const size_t ob1 = ((size_t)bb * TT + qrow1) * (HH * HDIM) + h * HDIM;
#pragma unroll
    for (int nt = 0; nt < 8; nt++) {
        const int c0 = nt * 8 + 2 * tg;
        Og[ob0 + c0]     = oacc[nt][0] * inv0;
        Og[ob0 + c0 + 1] = oacc[nt][1] * inv0;
        Og[ob1 + c0]     = oacc[nt][2] * inv1;
        Og[ob1 + c0 + 1] = oacc[nt][3] * inv1;
    }
}

// ---------------------------------------------------------------------------
extern "C" void kernel_launch(void* const* d_in, const int* in_sizes, int n_in,
                              void* d_out, int out_size) {
    const float* x  = (const float*)d_in[0];
    const float* Wq = (const float*)d_in[1];
    const float* Wk = (const float*)d_in[2];
    const float* Wv = (const float*)d_in[3];
    const float* Wo = (const float*)d_in[4];
    const float* bo = (const float*)d_in[5];
    if (n_in >= 6) {
        const float* big[8]; int nb = 0;
        const float* xx = 0; const float* bb = 0;
        for (int i = 0; i < n_in && i < 8; i++) {
            if (in_sizes[i] == BB * TT * DD)           xx = (const float*)d_in[i];
            else if (in_sizes[i] == DD)                bb = (const float*)d_in[i];
            else if (in_sizes[i] == DD * DD && nb < 8) big[nb++] = (const float*)d_in[i];
        }
        if (xx && bb && nb == 4) {
            x = xx; bo = bb;
            Wq = big[0]; Wk = big[1]; Wv = big[2]; Wo = big[3];
        }
    }
    float* out = (float*)d_out;
    (void)out_size;

    qkv_mma_kernel<<<dim3(MM / 128, NQ / 128, 3), 256>>>(x, Wq, Wk, Wv);
    attn_mma_kernel<<<dim3(BB * HH, TT / 64), 128>>>();
    out_mma_kernel<<<dim3(MM / 128, DD / 128), 256>>>(Wo, bo, out);
}

// round 14
// speedup vs baseline: 1.7113x; 1.7113x over previous
#include <cuda_runtime.h>
#include <cuda_bf16.h>
#include <cstdint>

#define BB   2
#define TT   2048
#define DD   1024
#define HH   16
#define HDIM 64
#define MM   (BB*TT)          // 4096
#define NQ   (HH*HDIM)        // 1024
#define SZ   (BB*HH*TT*HDIM)  // 4,194,304

// One scratch array: [0]=q, [1]=k, [2]=v, [3]=attention output
__device__ __align__(256) float g_scratch[4ull * SZ];

// ======================= mma helpers =======================================
__device__ __forceinline__ void mma_tf32(float* d, const uint32_t* a,
                                         const uint32_t* b) {
    asm volatile(
        "mma.sync.aligned.m16n8k8.row.col.f32.tf32.tf32.f32 "
        "{%0,%1,%2,%3}, {%4,%5,%6,%7}, {%8,%9}, {%0,%1,%2,%3};"
        : "+f"(d[0]), "+f"(d[1]), "+f"(d[2]), "+f"(d[3])
        : "r"(a[0]), "r"(a[1]), "r"(a[2]), "r"(a[3]), "r"(b[0]), "r"(b[1]));
}
__device__ __forceinline__ void mma_bf16(float* d, const uint32_t* a,
                                         const uint32_t* b) {
    asm volatile(
        "mma.sync.aligned.m16n8k16.row.col.f32.bf16.bf16.f32 "
        "{%0,%1,%2,%3}, {%4,%5,%6,%7}, {%8,%9}, {%0,%1,%2,%3};"
        : "+f"(d[0]), "+f"(d[1]), "+f"(d[2]), "+f"(d[3])
        : "r"(a[0]), "r"(a[1]), "r"(a[2]), "r"(a[3]), "r"(b[0]), "r"(b[1]));
}
__device__ __forceinline__ float hi_part(float x) {
    return __uint_as_float(__float_as_uint(x) & 0xFFFFE000u);
}
__device__ __forceinline__ float bfround(float x) {
    return __bfloat162float(__float2bfloat16_rn(x));
}
__device__ __forceinline__ uint32_t packbf(float a, float b) {
    __nv_bfloat162 t = __floats2bfloat162_rn(a, b);
    return *reinterpret_cast<uint32_t*>(&t);
}

// =================== bf16 GEMM smem layout =================================
// A: [row(128)][kp(8)] stride 12 (uint32 = bf16 k-pair)  -> conflict-free reads
// B: [kp(8)][n(128)]   stride 136                        -> conflict-free reads
#define ABSTR 12
#define BBSTR 136
struct GemmSmemBF {
    uint32_t Ah[128 * ABSTR];   // 6 KB
    uint32_t Al[128 * ABSTR];
    uint32_t Bh[8 * BBSTR];     // 4.25 KB
    uint32_t Bl[8 * BBSTR];
};

// One K-chunk of 16: 16 acc tiles x 3 split products, m16n8k16.
__device__ __forceinline__ void mma_chunk_bf(const GemmSmemBF& sm, int wid,
                                             int lane, float acc[4][4][4]) {
    const int warp_m = (wid >> 2) * 64;
    const int warp_n = (wid & 3) * 32;
    const int g  = lane >> 2;
    const int tg = lane & 3;

    uint32_t bh[4][2], bl[4][2];
#pragma unroll
    for (int nt = 0; nt < 4; nt++) {
        const int n0 = warp_n + nt * 8 + g;
        bh[nt][0] = sm.Bh[tg * BBSTR + n0];
        bh[nt][1] = sm.Bh[(tg + 4) * BBSTR + n0];
        bl[nt][0] = sm.Bl[tg * BBSTR + n0];
        bl[nt][1] = sm.Bl[(tg + 4) * BBSTR + n0];
    }
#pragma unroll
    for (int mt = 0; mt < 4; mt++) {
        const int r0 = warp_m + mt * 16 + g;
        uint32_t ah[4], al[4];
        ah[0] = sm.Ah[r0 * ABSTR + tg];
        ah[1] = sm.Ah[(r0 + 8) * ABSTR + tg];
        ah[2] = sm.Ah[r0 * ABSTR + tg + 4];
        ah[3] = sm.Ah[(r0 + 8) * ABSTR + tg + 4];
        al[0] = sm.Al[r0 * ABSTR + tg];
        al[1] = sm.Al[(r0 + 8) * ABSTR + tg];
        al[2] = sm.Al[r0 * ABSTR + tg + 4];
        al[3] = sm.Al[(r0 + 8) * ABSTR + tg + 4];
#pragma unroll
        for (int nt = 0; nt < 4; nt++) {
            mma_bf16(acc[mt][nt], ah, bh[nt]);
            mma_bf16(acc[mt][nt], ah, bl[nt]);
            mma_bf16(acc[mt][nt], al, bh[nt]);
        }
    }
}

// Store A float4 (row, k=c4..c4+3) as two k-pair words (hi & lo arrays)
__device__ __forceinline__ void store_a_bf(GemmSmemBF& sm, int row, int c4,
                                           float4 av) {
    const int kp = c4 >> 1;
    uint32_t h0 = packbf(av.x, av.y);
    uint32_t h1 = packbf(av.z, av.w);
    uint32_t l0 = packbf(av.x - bfround(av.x), av.y - bfround(av.y));
    uint32_t l1 = packbf(av.z - bfround(av.z), av.w - bfround(av.w));
    *reinterpret_cast<uint2*>(&sm.Ah[row * ABSTR + kp]) = make_uint2(h0, h1);
    *reinterpret_cast<uint2*>(&sm.Al[row * ABSTR + kp]) = make_uint2(l0, l1);
}
// Store B k-pair (two float4 rows k, k+1 at n4..n4+3)
__device__ __forceinline__ void store_b_bf(GemmSmemBF& sm, int kp, int n4,
                                           float4 b0, float4 b1) {
    const float x0[4] = {b0.x, b0.y, b0.z, b0.w};
    const float x1[4] = {b1.x, b1.y, b1.z, b1.w};
    uint32_t wh[4], wl[4];
#pragma unroll
    for (int j = 0; j < 4; j++) {
        wh[j] = packbf(x0[j], x1[j]);
        wl[j] = packbf(x0[j] - bfround(x0[j]), x1[j] - bfround(x1[j]));
    }
    *reinterpret_cast<uint4*>(&sm.Bh[kp * BBSTR + n4]) =
        make_uint4(wh[0], wh[1], wh[2], wh[3]);
    *reinterpret_cast<uint4*>(&sm.Bl[kp * BBSTR + n4]) =
        make_uint4(wl[0], wl[1], wl[2], wl[3]);
}

// ---------------------------------------------------------------------------
// QKV projection (bf16 tensor). Grid (32, 8, 3), block 256, 2 CTAs/SM.
// ---------------------------------------------------------------------------
__global__ __launch_bounds__(256, 2)
void qkv_mma_kernel(const float* __restrict__ x,
                    const float* __restrict__ Wq,
                    const float* __restrict__ Wk,
                    const float* __restrict__ Wv) {
    __shared__ GemmSmemBF sm;
    const float* W = (blockIdx.z == 0) ? Wq : (blockIdx.z == 1) ? Wk : Wv;
    float* out = g_scratch + (size_t)blockIdx.z * SZ;

    const int bm   = blockIdx.x * 128;
    const int bn   = blockIdx.y * 128;
    const int tid  = threadIdx.x;
    const int wid  = tid >> 5;
    const int lane = tid & 31;

    // B-load geometry: thread -> (k pair, 4 n's)
    const int bn4   = (tid & 31) << 2;
    const int bkp   = tid >> 5;           // 0..7
    const int nglob = bn + bn4;
    const size_t bcol = ((size_t)(nglob >> 6) * DD) * HDIM + (nglob & 63);

    float acc[4][4][4];
#pragma unroll
    for (int mt = 0; mt < 4; mt++)
#pragma unroll
        for (int nt = 0; nt < 4; nt++)
#pragma unroll
            for (int r = 0; r < 4; r++) acc[mt][nt][r] = 0.f;

    for (int c = 0; c < 64; c++) {
        const int k0 = c * 16;
        // stage global loads
        float4 av[2]; int arow[2], ac4[2];
#pragma unroll
        for (int it = 0; it < 2; it++) {
            int idx = tid + it * 256;
            arow[it] = idx >> 2;
            ac4[it]  = (idx & 3) << 2;
            av[it] = *reinterpret_cast<const float4*>(
                &x[(size_t)(bm + arow[it]) * DD + k0 + ac4[it]]);
        }
        const int d0 = k0 + bkp * 2;
        float4 bv0 = *reinterpret_cast<const float4*>(&W[bcol + (size_t)d0 * HDIM]);
        float4 bv1 = *reinterpret_cast<const float4*>(&W[bcol + (size_t)(d0 + 1) * HDIM]);

        if (c > 0) __syncthreads();
#pragma unroll
        for (int it = 0; it < 2; it++) store_a_bf(sm, arow[it], ac4[it], av[it]);
        store_b_bf(sm, bkp, bn4, bv0, bv1);
        __syncthreads();
        mma_chunk_bf(sm, wid, lane, acc);
    }

    const int warp_m = (wid >> 2) * 64;
    const int warp_n = (wid & 3) * 32;
    const int g  = lane >> 2;
    const int tg = lane & 3;
#pragma unroll
    for (int mt = 0; mt < 4; mt++) {
#pragma unroll
        for (int nt = 0; nt < 4; nt++) {
#pragma unroll
            for (int r = 0; r < 4; r++) {
                int m = bm + warp_m + mt * 16 + g + ((r >= 2) ? 8 : 0);
                int n = bn + warp_n + nt * 8 + tg * 2 + (r & 1);
                int b = m >> 11, t = m & 2047;
                out[(((size_t)b * HH + (n >> 6)) * TT + t) * HDIM + (n & 63)] =
                    acc[mt][nt][r];
            }
        }
    }
}

// ---------------------------------------------------------------------------
// Output projection (bf16 tensor). Grid (32, 8), block 256, 2 CTAs/SM.
// ---------------------------------------------------------------------------
__global__ __launch_bounds__(256, 2)
void out_mma_kernel(const float* __restrict__ Wo,
                    const float* __restrict__ bo,
                    float* __restrict__ outp) {
    __shared__ GemmSmemBF sm;
    const float* A = g_scratch + 3ull * SZ;

    const int bm   = blockIdx.x * 128;
    const int bn   = blockIdx.y * 128;
    const int tid  = threadIdx.x;
    const int wid  = tid >> 5;
    const int lane = tid & 31;

    const int bn4 = (tid & 31) << 2;
    const int bkp = tid >> 5;

    float acc[4][4][4];
#pragma unroll
    for (int mt = 0; mt < 4; mt++)
#pragma unroll
        for (int nt = 0; nt < 4; nt++)
#pragma unroll
            for (int r = 0; r < 4; r++) acc[mt][nt][r] = 0.f;

    for (int c = 0; c < 64; c++) {
        const int k0 = c * 16;
        float4 av[2]; int arow[2], ac4[2];
#pragma unroll
        for (int it = 0; it < 2; it++) {
            int idx = tid + it * 256;
            arow[it] = idx >> 2;
            ac4[it]  = (idx & 3) << 2;
            av[it] = *reinterpret_cast<const float4*>(
                &A[(size_t)(bm + arow[it]) * DD + k0 + ac4[it]]);
        }
        const int d0 = k0 + bkp * 2;
        float4 bv0 = *reinterpret_cast<const float4*>(&Wo[(size_t)d0 * DD + bn + bn4]);
        float4 bv1 = *reinterpret_cast<const float4*>(&Wo[(size_t)(d0 + 1) * DD + bn + bn4]);

        if (c > 0) __syncthreads();
#pragma unroll
        for (int it = 0; it < 2; it++) store_a_bf(sm, arow[it], ac4[it], av[it]);
        store_b_bf(sm, bkp, bn4, bv0, bv1);
        __syncthreads();
        mma_chunk_bf(sm, wid, lane, acc);
    }

    const int warp_m = (wid >> 2) * 64;
    const int warp_n = (wid & 3) * 32;
    const int g  = lane >> 2;
    const int tg = lane & 3;
#pragma unroll
    for (int mt = 0; mt < 4; mt++) {
#pragma unroll
        for (int nt = 0; nt < 4; nt++) {
#pragma unroll
            for (int r = 0; r < 4; r++) {
                int m = bm + warp_m + mt * 16 + g + ((r >= 2) ? 8 : 0);
                int n = bn + warp_n + nt * 8 + tg * 2 + (r & 1);
                outp[(size_t)m * DD + n] = acc[mt][nt][r] + bo[n];
            }
        }
    }
}

// ---------------------------------------------------------------------------
// Tensor-core flash attention (causal), split-tf32, online softmax.
// EXACT R10 version (proven, 958us run). Grid: (B*H, T/64). Block: 128.
// ---------------------------------------------------------------------------
#define KSTR 68
#define VSTR 72
#define PSTR 36

__global__ __launch_bounds__(128)
void attn_mma_kernel() {
    __shared__ float sU[4608];
    __shared__ float sVh[32 * VSTR];
    __shared__ float sVl[32 * VSTR];

    float* Kh = sU;
    float* Kl = sU + 32 * KSTR;
    float* Ph = sU;
    float* Pl = sU + 64 * PSTR;

    const int bh = blockIdx.x;
    const int qt = blockIdx.y;
    const int bb = bh >> 4;
    const int h  = bh & 15;
    const size_t base = (size_t)bh * TT * HDIM;
    const float* Qg = g_scratch + 0ull * SZ + base;
    const float* Kg = g_scratch + 1ull * SZ + base;
    const float* Vg = g_scratch + 2ull * SZ + base;
    float*       Og = g_scratch + 3ull * SZ;

    const int tid  = threadIdx.x;
    const int wid  = tid >> 5;
    const int lane = tid & 31;
    const int g    = lane >> 2;
    const int tg   = lane & 3;
    const int wr   = wid * 16;
    const int qrow0 = qt * 64 + wr + g;
    const int qrow1 = qrow0 + 8;

    uint32_t qh[8][4], ql[8][4];
#pragma unroll
    for (int ks = 0; ks < 8; ks++) {
        const int kb = ks * 8;
#pragma unroll
        for (int r = 0; r < 4; r++) {
            int row = (r & 1) ? qrow1 : qrow0;
            int col = kb + tg + ((r >= 2) ? 4 : 0);
            float v = __ldg(&Qg[(size_t)row * HDIM + col]);
            float hv = hi_part(v);
            qh[ks][r] = __float_as_uint(hv);
            ql[ks][r] = __float_as_uint(v - hv);
        }
    }

    float oacc[8][4];
#pragma unroll
    for (int nt = 0; nt < 8; nt++)
#pragma unroll
        for (int r = 0; r < 4; r++) oacc[nt][r] = 0.f;
    float mrow0 = -1e30f, mrow1 = -1e30f, lrow0 = 0.f, lrow1 = 0.f;
    const float scale = 0.125f;

    const int kt_max = 2 * qt + 1;
    for (int kt = 0; kt <= kt_max; kt++) {
        __syncthreads();
#pragma unroll
        for (int it = 0; it < 4; it++) {
            int idx = tid + it * 128;
            int row = idx >> 4, c4 = (idx & 15) << 2;
            float4 kv = *reinterpret_cast<const float4*>(
                &Kg[(size_t)(kt * 32 + row) * HDIM + c4]);
            float4 h4, l4;
            h4.x = hi_part(kv.x); l4.x = kv.x - h4.x;
            h4.y = hi_part(kv.y); l4.y = kv.y - h4.y;
            h4.z = hi_part(kv.z); l4.z = kv.z - h4.z;
            h4.w = hi_part(kv.w); l4.w = kv.w - h4.w;
            *reinterpret_cast<float4*>(&Kh[row * KSTR + c4]) = h4;
            *reinterpret_cast<float4*>(&Kl[row * KSTR + c4]) = l4;
            float4 vv = *reinterpret_cast<const float4*>(
                &Vg[(size_t)(kt * 32 + row) * HDIM + c4]);
            h4.x = hi_part(vv.x); l4.x = vv.x - h4.x;
            h4.y = hi_part(vv.y); l4.y = vv.y - h4.y;
            h4.z = hi_part(vv.z); l4.z = vv.z - h4.z;
            h4.w = hi_part(vv.w); l4.w = vv.w - h4.w;
            *reinterpret_cast<float4*>(&sVh[row * VSTR + c4]) = h4;
            *reinterpret_cast<float4*>(&sVl[row * VSTR + c4]) = l4;
        }
        __syncthreads();

        float sacc[4][4];
#pragma unroll
        for (int nt = 0; nt < 4; nt++)
#pragma unroll
            for (int r = 0; r < 4; r++) sacc[nt][r] = 0.f;
#pragma unroll
        for (int ks = 0; ks < 8; ks++) {
            const int kb = ks * 8;
#pragma unroll
            for (int nt = 0; nt < 4; nt++) {
                const int n0 = nt * 8 + g;
                uint32_t bhf[2], blf[2];
                bhf[0] = __float_as_uint(Kh[n0 * KSTR + kb + tg]);
                bhf[1] = __float_as_uint(Kh[n0 * KSTR + kb + tg + 4]);
                blf[0] = __float_as_uint(Kl[n0 * KSTR + kb + tg]);
                blf[1] = __float_as_uint(Kl[n0 * KSTR + kb + tg + 4]);
                mma_tf32(sacc[nt], qh[ks], bhf);
                mma_tf32(sacc[nt], qh[ks], blf);
                mma_tf32(sacc[nt], ql[ks], bhf);
            }
        }

        float mt0 = -1e30f, mt1 = -1e30f;
#pragma unroll
        for (int nt = 0; nt < 4; nt++) {
#pragma unroll
            for (int j = 0; j < 2; j++) {
                int scol = kt * 32 + nt * 8 + 2 * tg + j;
                float sv0 = sacc[nt][j] * scale;
                if (scol > qrow0) sv0 = -1e30f;
                sacc[nt][j] = sv0;
                mt0 = fmaxf(mt0, sv0);
                float sv1 = sacc[nt][2 + j] * scale;
                if (scol > qrow1) sv1 = -1e30f;
                sacc[nt][2 + j] = sv1;
                mt1 = fmaxf(mt1, sv1);
            }
        }
        mt0 = fmaxf(mt0, __shfl_xor_sync(0xffffffffu, mt0, 1));
        mt0 = fmaxf(mt0, __shfl_xor_sync(0xffffffffu, mt0, 2));
        mt1 = fmaxf(mt1, __shfl_xor_sync(0xffffffffu, mt1, 1));
        mt1 = fmaxf(mt1, __shfl_xor_sync(0xffffffffu, mt1, 2));

        float mn0 = fmaxf(mrow0, mt0), mn1 = fmaxf(mrow1, mt1);
        float corr0 = __expf(mrow0 - mn0), corr1 = __expf(mrow1 - mn1);
        mrow0 = mn0; mrow1 = mn1;
        float sum0 = 0.f, sum1 = 0.f;
#pragma unroll
        for (int nt = 0; nt < 4; nt++) {
#pragma unroll
            for (int j = 0; j < 2; j++) {
                float p0 = __expf(sacc[nt][j] - mn0);
                sacc[nt][j] = p0; sum0 += p0;
                float p1 = __expf(sacc[nt][2 + j] - mn1);
                sacc[nt][2 + j] = p1; sum1 += p1;
            }
        }
        sum0 += __shfl_xor_sync(0xffffffffu, sum0, 1);
        sum0 += __shfl_xor_sync(0xffffffffu, sum0, 2);
        sum1 += __shfl_xor_sync(0xffffffffu, sum1, 1);
        sum1 += __shfl_xor_sync(0xffffffffu, sum1, 2);
        lrow0 = lrow0 * corr0 + sum0;
        lrow1 = lrow1 * corr1 + sum1;
#pragma unroll
        for (int nt = 0; nt < 8; nt++) {
            oacc[nt][0] *= corr0; oacc[nt][1] *= corr0;
            oacc[nt][2] *= corr1; oacc[nt][3] *= corr1;
        }

        __syncthreads();

#pragma unroll
        for (int nt = 0; nt < 4; nt++) {
            const int c0 = nt * 8 + 2 * tg;
            float p;
            p = sacc[nt][0];
            Ph[(wr + g) * PSTR + c0]     = hi_part(p);
            Pl[(wr + g) * PSTR + c0]     = p - hi_part(p);
            p = sacc[nt][1];
            Ph[(wr + g) * PSTR + c0 + 1] = hi_part(p);
            Pl[(wr + g) * PSTR + c0 + 1] = p - hi_part(p);
            p = sacc[nt][2];
            Ph[(wr + g + 8) * PSTR + c0]     = hi_part(p);
            Pl[(wr + g + 8) * PSTR + c0]     = p - hi_part(p);
            p = sacc[nt][3];
            Ph[(wr + g + 8) * PSTR + c0 + 1] = hi_part(p);
            Pl[(wr + g + 8) * PSTR + c0 + 1] = p - hi_part(p);
        }
        __syncwarp();

#pragma unroll
        for (int ks = 0; ks < 4; ks++) {
            const int kb = ks * 8;
            uint32_t pa[4], pb[4];
            pa[0] = __float_as_uint(Ph[(wr + g) * PSTR + kb + tg]);
            pa[1] = __float_as_uint(Ph[(wr + g + 8) * PSTR + kb + tg]);
            pa[2] = __float_as_uint(Ph[(wr + g) * PSTR + kb + tg + 4]);
            pa[3] = __float_as_uint(Ph[(wr + g + 8) * PSTR + kb + tg + 4]);
            pb[0] = __float_as_uint(Pl[(wr + g) * PSTR + kb + tg]);
            pb[1] = __float_as_uint(Pl[(wr + g + 8) * PSTR + kb + tg]);
            pb[2] = __float_as_uint(Pl[(wr + g) * PSTR + kb + tg + 4]);
            pb[3] = __float_as_uint(Pl[(wr + g + 8) * PSTR + kb + tg + 4]);
#pragma unroll
            for (int nt = 0; nt < 8; nt++) {
                const int n0 = nt * 8 + g;
                uint32_t vh[2], vl[2];
                vh[0] = __float_as_uint(sVh[(kb + tg) * VSTR + n0]);
                vh[1] = __float_as_uint(sVh[(kb + 4 + tg) * VSTR + n0]);
                vl[0] = __float_as_uint(sVl[(kb + tg) * VSTR + n0]);
                vl[1] = __float_as_uint(sVl[(kb + 4 + tg) * VSTR + n0]);
                mma_tf32(oacc[nt], pa, vh);
                mma_tf32(oacc[nt], pa, vl);
                mma_tf32(oacc[nt], pb, vh);
            }
        }
    }

    const float inv0 = 1.f / lrow0;
    const float inv1 = 1.f / lrow1;
    const size_t ob0 = ((size_t)bb * TT + qrow0) * (HH * HDIM) + h * HDIM;
    const size_t ob1 = ((size_t)bb * TT + qrow1) * (HH * HDIM) + h * HDIM;
#pragma unroll
    for (int nt = 0; nt < 8; nt++) {
        const int c0 = nt * 8 + 2 * tg;
        Og[ob0 + c0]     = oacc[nt][0] * inv0;
        Og[ob0 + c0 + 1] = oacc[nt][1] * inv0;
        Og[ob1 + c0]     = oacc[nt][2] * inv1;
        Og[ob1 + c0 + 1] = oacc[nt][3] * inv1;
    }
}

// ---------------------------------------------------------------------------
extern "C" void kernel_launch(void* const* d_in, const int* in_sizes, int n_in,
                              void* d_out, int out_size) {
    const float* x  = (const float*)d_in[0];
    const float* Wq = (const float*)d_in[1];
    const float* Wk = (const float*)d_in[2];
    const float* Wv = (const float*)d_in[3];
    const float* Wo = (const float*)d_in[4];
    const float* bo = (const float*)d_in[5];
    if (n_in >= 6) {
        const float* big[8]; int nb = 0;
        const float* xx = 0; const float* bb = 0;
        for (int i = 0; i < n_in && i < 8; i++) {
            if (in_sizes[i] == BB * TT * DD)           xx = (const float*)d_in[i];
            else if (in_sizes[i] == DD)                bb = (const float*)d_in[i];
            else if (in_sizes[i] == DD * DD && nb < 8) big[nb++] = (const float*)d_in[i];
        }
        if (xx && bb && nb == 4) {
            x = xx; bo = bb;
            Wq = big[0]; Wk = big[1]; Wv = big[2]; Wo = big[3];
        }
    }
    float* out = (float*)d_out;
    (void)out_size;

    qkv_mma_kernel<<<dim3(MM / 128, NQ / 128, 3), 256>>>(x, Wq, Wk, Wv);
    attn_mma_kernel<<<dim3(BB * HH, TT / 64), 128>>>();
    out_mma_kernel<<<dim3(MM / 128, DD / 128), 256>>>(Wo, bo, out);
}

// round 16
// speedup vs baseline: 2.1677x; 1.2667x over previous
#include <cuda_runtime.h>
#include <cuda_bf16.h>
#include <cstdint>

#define BB   2
#define TT   2048
#define DD   1024
#define HH   16
#define HDIM 64
#define MM   (BB*TT)          // 4096
#define NQ   (HH*HDIM)        // 1024
#define SZ   (BB*HH*TT*HDIM)  // 4,194,304

// One scratch array: [0]=q, [1]=k, [2]=v, [3]=attention output
__device__ __align__(256) float g_scratch[4ull * SZ];

// ======================= mma helpers =======================================
__device__ __forceinline__ void mma_bf16(float* d, const uint32_t* a,
                                         const uint32_t* b) {
    asm volatile(
        "mma.sync.aligned.m16n8k16.row.col.f32.bf16.bf16.f32 "
        "{%0,%1,%2,%3}, {%4,%5,%6,%7}, {%8,%9}, {%0,%1,%2,%3};"
        : "+f"(d[0]), "+f"(d[1]), "+f"(d[2]), "+f"(d[3])
        : "r"(a[0]), "r"(a[1]), "r"(a[2]), "r"(a[3]), "r"(b[0]), "r"(b[1]));
}
__device__ __forceinline__ float bfround(float x) {
    return __bfloat162float(__float2bfloat16_rn(x));
}
__device__ __forceinline__ uint32_t packbf(float a, float b) {
    __nv_bfloat162 t = __floats2bfloat162_rn(a, b);
    return *reinterpret_cast<uint32_t*>(&t);
}

// =================== bf16 GEMM smem layout (R14, proven) ===================
#define ABSTR 12
#define BBSTR 136
struct GemmSmemBF {
    uint32_t Ah[128 * ABSTR];
    uint32_t Al[128 * ABSTR];
    uint32_t Bh[8 * BBSTR];
    uint32_t Bl[8 * BBSTR];
};

__device__ __forceinline__ void mma_chunk_bf(const GemmSmemBF& sm, int wid,
                                             int lane, float acc[4][4][4]) {
    const int warp_m = (wid >> 2) * 64;
    const int warp_n = (wid & 3) * 32;
    const int g  = lane >> 2;
    const int tg = lane & 3;

    uint32_t bh[4][2], bl[4][2];
#pragma unroll
    for (int nt = 0; nt < 4; nt++) {
        const int n0 = warp_n + nt * 8 + g;
        bh[nt][0] = sm.Bh[tg * BBSTR + n0];
        bh[nt][1] = sm.Bh[(tg + 4) * BBSTR + n0];
        bl[nt][0] = sm.Bl[tg * BBSTR + n0];
        bl[nt][1] = sm.Bl[(tg + 4) * BBSTR + n0];
    }
#pragma unroll
    for (int mt = 0; mt < 4; mt++) {
        const int r0 = warp_m + mt * 16 + g;
        uint32_t ah[4], al[4];
        ah[0] = sm.Ah[r0 * ABSTR + tg];
        ah[1] = sm.Ah[(r0 + 8) * ABSTR + tg];
        ah[2] = sm.Ah[r0 * ABSTR + tg + 4];
        ah[3] = sm.Ah[(r0 + 8) * ABSTR + tg + 4];
        al[0] = sm.Al[r0 * ABSTR + tg];
        al[1] = sm.Al[(r0 + 8) * ABSTR + tg];
        al[2] = sm.Al[r0 * ABSTR + tg + 4];
        al[3] = sm.Al[(r0 + 8) * ABSTR + tg + 4];
#pragma unroll
        for (int nt = 0; nt < 4; nt++) {
            mma_bf16(acc[mt][nt], ah, bh[nt]);
            mma_bf16(acc[mt][nt], ah, bl[nt]);
            mma_bf16(acc[mt][nt], al, bh[nt]);
        }
    }
}

__device__ __forceinline__ void store_a_bf(GemmSmemBF& sm, int row, int c4,
                                           float4 av) {
    const int kp = c4 >> 1;
    uint32_t h0 = packbf(av.x, av.y);
    uint32_t h1 = packbf(av.z, av.w);
    uint32_t l0 = packbf(av.x - bfround(av.x), av.y - bfround(av.y));
    uint32_t l1 = packbf(av.z - bfround(av.z), av.w - bfround(av.w));
    *reinterpret_cast<uint2*>(&sm.Ah[row * ABSTR + kp]) = make_uint2(h0, h1);
    *reinterpret_cast<uint2*>(&sm.Al[row * ABSTR + kp]) = make_uint2(l0, l1);
}
__device__ __forceinline__ void store_b_bf(GemmSmemBF& sm, int kp, int n4,
                                           float4 b0, float4 b1) {
    const float x0[4] = {b0.x, b0.y, b0.z, b0.w};
    const float x1[4] = {b1.x, b1.y, b1.z, b1.w};
    uint32_t wh[4], wl[4];
#pragma unroll
    for (int j = 0; j < 4; j++) {
        wh[j] = packbf(x0[j], x1[j]);
        wl[j] = packbf(x0[j] - bfround(x0[j]), x1[j] - bfround(x1[j]));
    }
    *reinterpret_cast<uint4*>(&sm.Bh[kp * BBSTR + n4]) =
        make_uint4(wh[0], wh[1], wh[2], wh[3]);
    *reinterpret_cast<uint4*>(&sm.Bl[kp * BBSTR + n4]) =
        make_uint4(wl[0], wl[1], wl[2], wl[3]);
}

// ---------------------------------------------------------------------------
// QKV projection (bf16 tensor). Grid (32, 8, 3), block 256, 2 CTAs/SM.
// ---------------------------------------------------------------------------
__global__ __launch_bounds__(256, 2)
void qkv_mma_kernel(const float* __restrict__ x,
                    const float* __restrict__ Wq,
                    const float* __restrict__ Wk,
                    const float* __restrict__ Wv) {
    __shared__ GemmSmemBF sm;
    const float* W = (blockIdx.z == 0) ? Wq : (blockIdx.z == 1) ? Wk : Wv;
    float* out = g_scratch + (size_t)blockIdx.z * SZ;

    const int bm   = blockIdx.x * 128;
    const int bn   = blockIdx.y * 128;
    const int tid  = threadIdx.x;
    const int wid  = tid >> 5;
    const int lane = tid & 31;

    const int bn4   = (tid & 31) << 2;
    const int bkp   = tid >> 5;
    const int nglob = bn + bn4;
    const size_t bcol = ((size_t)(nglob >> 6) * DD) * HDIM + (nglob & 63);

    float acc[4][4][4];
#pragma unroll
    for (int mt = 0; mt < 4; mt++)
#pragma unroll
        for (int nt = 0; nt < 4; nt++)
#pragma unroll
            for (int r = 0; r < 4; r++) acc[mt][nt][r] = 0.f;

    for (int c = 0; c < 64; c++) {
        const int k0 = c * 16;
        float4 av[2]; int arow[2], ac4[2];
#pragma unroll
        for (int it = 0; it < 2; it++) {
            int idx = tid + it * 256;
            arow[it] = idx >> 2;
            ac4[it]  = (idx & 3) << 2;
            av[it] = *reinterpret_cast<const float4*>(
                &x[(size_t)(bm + arow[it]) * DD + k0 + ac4[it]]);
        }
        const int d0 = k0 + bkp * 2;
        float4 bv0 = *reinterpret_cast<const float4*>(&W[bcol + (size_t)d0 * HDIM]);
        float4 bv1 = *reinterpret_cast<const float4*>(&W[bcol + (size_t)(d0 + 1) * HDIM]);

        if (c > 0) __syncthreads();
#pragma unroll
        for (int it = 0; it < 2; it++) store_a_bf(sm, arow[it], ac4[it], av[it]);
        store_b_bf(sm, bkp, bn4, bv0, bv1);
        __syncthreads();
        mma_chunk_bf(sm, wid, lane, acc);
    }

    const int warp_m = (wid >> 2) * 64;
    const int warp_n = (wid & 3) * 32;
    const int g  = lane >> 2;
    const int tg = lane & 3;
#pragma unroll
    for (int mt = 0; mt < 4; mt++) {
#pragma unroll
        for (int nt = 0; nt < 4; nt++) {
#pragma unroll
            for (int r = 0; r < 4; r++) {
                int m = bm + warp_m + mt * 16 + g + ((r >= 2) ? 8 : 0);
                int n = bn + warp_n + nt * 8 + tg * 2 + (r & 1);
                int b = m >> 11, t = m & 2047;
                out[(((size_t)b * HH + (n >> 6)) * TT + t) * HDIM + (n & 63)] =
                    acc[mt][nt][r];
            }
        }
    }
}

// ---------------------------------------------------------------------------
// Output projection (bf16 tensor). Grid (32, 8), block 256, 2 CTAs/SM.
// ---------------------------------------------------------------------------
__global__ __launch_bounds__(256, 2)
void out_mma_kernel(const float* __restrict__ Wo,
                    const float* __restrict__ bo,
                    float* __restrict__ outp) {
    __shared__ GemmSmemBF sm;
    const float* A = g_scratch + 3ull * SZ;

    const int bm   = blockIdx.x * 128;
    const int bn   = blockIdx.y * 128;
    const int tid  = threadIdx.x;
    const int wid  = tid >> 5;
    const int lane = tid & 31;

    const int bn4 = (tid & 31) << 2;
    const int bkp = tid >> 5;

    float acc[4][4][4];
#pragma unroll
    for (int mt = 0; mt < 4; mt++)
#pragma unroll
        for (int nt = 0; nt < 4; nt++)
#pragma unroll
            for (int r = 0; r < 4; r++) acc[mt][nt][r] = 0.f;

    for (int c = 0; c < 64; c++) {
        const int k0 = c * 16;
        float4 av[2]; int arow[2], ac4[2];
#pragma unroll
        for (int it = 0; it < 2; it++) {
            int idx = tid + it * 256;
            arow[it] = idx >> 2;
            ac4[it]  = (idx & 3) << 2;
            av[it] = *reinterpret_cast<const float4*>(
                &A[(size_t)(bm + arow[it]) * DD + k0 + ac4[it]]);
        }
        const int d0 = k0 + bkp * 2;
        float4 bv0 = *reinterpret_cast<const float4*>(&Wo[(size_t)d0 * DD + bn + bn4]);
        float4 bv1 = *reinterpret_cast<const float4*>(&Wo[(size_t)(d0 + 1) * DD + bn + bn4]);

        if (c > 0) __syncthreads();
#pragma unroll
        for (int it = 0; it < 2; it++) store_a_bf(sm, arow[it], ac4[it], av[it]);
        store_b_bf(sm, bkp, bn4, bv0, bv1);
        __syncthreads();
        mma_chunk_bf(sm, wid, lane, acc);
    }

    const int warp_m = (wid >> 2) * 64;
    const int warp_n = (wid & 3) * 32;
    const int g  = lane >> 2;
    const int tg = lane & 3;
#pragma unroll
    for (int mt = 0; mt < 4; mt++) {
#pragma unroll
        for (int nt = 0; nt < 4; nt++) {
#pragma unroll
            for (int r = 0; r < 4; r++) {
                int m = bm + warp_m + mt * 16 + g + ((r >= 2) ? 8 : 0);
                int n = bn + warp_n + nt * 8 + tg * 2 + (r & 1);
                outp[(size_t)m * DD + n] = acc[mt][nt][r] + bo[n];
            }
        }
    }
}

// ---------------------------------------------------------------------------
// bf16 tensor-core flash attention (causal), split hi/lo, online softmax.
// Grid: (B*H, T/64). Block: 128 threads = 4 warps; warp owns 16 query rows.
// K: [key(32)][kp(32)] stride 36; V: [keypair(16)][n(64)] stride 72;
// P: [row(64)][kp(16)] stride 20.  All conflict-free frag reads.
// ---------------------------------------------------------------------------
#define KSTRB 36
#define VSTRB 72
#define PSTRB 20

__global__ __launch_bounds__(128)
void attn_mma_kernel() {
    __shared__ uint32_t sKh[32 * KSTRB], sKl[32 * KSTRB];
    __shared__ uint32_t sVh[16 * VSTRB], sVl[16 * VSTRB];
    __shared__ uint32_t sPh[64 * PSTRB], sPl[64 * PSTRB];

    const int bh = blockIdx.x;
    const int qt = blockIdx.y;
    const int bb = bh >> 4;
    const int h  = bh & 15;
    const size_t base = (size_t)bh * TT * HDIM;
    const float* Qg = g_scratch + 0ull * SZ + base;
    const float* Kg = g_scratch + 1ull * SZ + base;
    const float* Vg = g_scratch + 2ull * SZ + base;
    float*       Og = g_scratch + 3ull * SZ;

    const int tid  = threadIdx.x;
    const int wid  = tid >> 5;
    const int lane = tid & 31;
    const int g    = lane >> 2;
    const int tg   = lane & 3;
    const int wr   = wid * 16;
    const int qrow0 = qt * 64 + wr + g;
    const int qrow1 = qrow0 + 8;

    // ---- load Q fragments: packed bf16 pairs, hi/lo ----
    uint32_t qh[4][4], ql[4][4];
#pragma unroll
    for (int ks = 0; ks < 4; ks++) {
#pragma unroll
        for (int r = 0; r < 4; r++) {
            int row = (r & 1) ? qrow1 : qrow0;
            int col = ks * 16 + ((r >= 2) ? 8 : 0) + 2 * tg;
            float2 v = *reinterpret_cast<const float2*>(
                &Qg[(size_t)row * HDIM + col]);
            qh[ks][r] = packbf(v.x, v.y);
            ql[ks][r] = packbf(v.x - bfround(v.x), v.y - bfround(v.y));
        }
    }

    float oacc[8][4];
#pragma unroll
    for (int nt = 0; nt < 8; nt++)
#pragma unroll
        for (int r = 0; r < 4; r++) oacc[nt][r] = 0.f;
    float mrow0 = -1e30f, mrow1 = -1e30f, lrow0 = 0.f, lrow1 = 0.f;
    const float scale = 0.125f;

    const int kt_max = 2 * qt + 1;
    for (int kt = 0; kt <= kt_max; kt++) {
        __syncthreads();   // prev iter readers done before overwrite
        // ---- K tile: 32 rows x 64 cols -> [key][kp] pairs ----
#pragma unroll
        for (int it = 0; it < 4; it++) {
            int idx = tid + it * 128;            // 0..511
            int row = idx >> 4, c4 = (idx & 15) << 2;
            float4 kv = *reinterpret_cast<const float4*>(
                &Kg[(size_t)(kt * 32 + row) * HDIM + c4]);
            uint32_t h0 = packbf(kv.x, kv.y);
            uint32_t h1 = packbf(kv.z, kv.w);
            uint32_t l0 = packbf(kv.x - bfround(kv.x), kv.y - bfround(kv.y));
            uint32_t l1 = packbf(kv.z - bfround(kv.z), kv.w - bfround(kv.w));
            *reinterpret_cast<uint2*>(&sKh[row * KSTRB + (c4 >> 1)]) =
                make_uint2(h0, h1);
            *reinterpret_cast<uint2*>(&sKl[row * KSTRB + (c4 >> 1)]) =
                make_uint2(l0, l1);
        }
        // ---- V tile: [keypair][n] ----
#pragma unroll
        for (int it = 0; it < 2; it++) {
            int idx = tid + it * 128;            // 0..255
            int kp = idx >> 4, n4 = (idx & 15) << 2;
            const int d0 = kt * 32 + kp * 2;
            float4 v0 = *reinterpret_cast<const float4*>(
                &Vg[(size_t)d0 * HDIM + n4]);
            float4 v1 = *reinterpret_cast<const float4*>(
                &Vg[(size_t)(d0 + 1) * HDIM + n4]);
            const float x0[4] = {v0.x, v0.y, v0.z, v0.w};
            const float x1[4] = {v1.x, v1.y, v1.z, v1.w};
            uint32_t wh[4], wl[4];
#pragma unroll
            for (int j = 0; j < 4; j++) {
                wh[j] = packbf(x0[j], x1[j]);
                wl[j] = packbf(x0[j] - bfround(x0[j]), x1[j] - bfround(x1[j]));
            }
            *reinterpret_cast<uint4*>(&sVh[kp * VSTRB + n4]) =
                make_uint4(wh[0], wh[1], wh[2], wh[3]);
            *reinterpret_cast<uint4*>(&sVl[kp * VSTRB + n4]) =
                make_uint4(wl[0], wl[1], wl[2], wl[3]);
        }
        __syncthreads();

        // ---- S = Q K^T (warp: 16 rows x 32 cols; 4 ks x 4 nt x 3) ----
        float sacc[4][4];
#pragma unroll
        for (int nt = 0; nt < 4; nt++)
#pragma unroll
            for (int r = 0; r < 4; r++) sacc[nt][r] = 0.f;
#pragma unroll
        for (int ks = 0; ks < 4; ks++) {
#pragma unroll
            for (int nt = 0; nt < 4; nt++) {
                const int n0 = nt * 8 + g;
                uint32_t bhf[2], blf[2];
                bhf[0] = sKh[n0 * KSTRB + ks * 8 + tg];
                bhf[1] = sKh[n0 * KSTRB + ks * 8 + tg + 4];
                blf[0] = sKl[n0 * KSTRB + ks * 8 + tg];
                blf[1] = sKl[n0 * KSTRB + ks * 8 + tg + 4];
                mma_bf16(sacc[nt], qh[ks], bhf);
                mma_bf16(sacc[nt], qh[ks], blf);
                mma_bf16(sacc[nt], ql[ks], bhf);
            }
        }

        // ---- scale + causal mask + online softmax ----
        float mt0 = -1e30f, mt1 = -1e30f;
#pragma unroll
        for (int nt = 0; nt < 4; nt++) {
#pragma unroll
            for (int j = 0; j < 2; j++) {
                int scol = kt * 32 + nt * 8 + 2 * tg + j;
                float sv0 = sacc[nt][j] * scale;
                if (scol > qrow0) sv0 = -1e30f;
                sacc[nt][j] = sv0;
                mt0 = fmaxf(mt0, sv0);
                float sv1 = sacc[nt][2 + j] * scale;
                if (scol > qrow1) sv1 = -1e30f;
                sacc[nt][2 + j] = sv1;
                mt1 = fmaxf(mt1, sv1);
            }
        }
        mt0 = fmaxf(mt0, __shfl_xor_sync(0xffffffffu, mt0, 1));
        mt0 = fmaxf(mt0, __shfl_xor_sync(0xffffffffu, mt0, 2));
        mt1 = fmaxf(mt1, __shfl_xor_sync(0xffffffffu, mt1, 1));
        mt1 = fmaxf(mt1, __shfl_xor_sync(0xffffffffu, mt1, 2));

        float mn0 = fmaxf(mrow0, mt0), mn1 = fmaxf(mrow1, mt1);
        float corr0 = __expf(mrow0 - mn0), corr1 = __expf(mrow1 - mn1);
        mrow0 = mn0; mrow1 = mn1;
        float sum0 = 0.f, sum1 = 0.f;
#pragma unroll
        for (int nt = 0; nt < 4; nt++) {
#pragma unroll
            for (int j = 0; j < 2; j++) {
                float p0 = __expf(sacc[nt][j] - mn0);
                sacc[nt][j] = p0; sum0 += p0;
                float p1 = __expf(sacc[nt][2 + j] - mn1);
                sacc[nt][2 + j] = p1; sum1 += p1;
            }
        }
        sum0 += __shfl_xor_sync(0xffffffffu, sum0, 1);
        sum0 += __shfl_xor_sync(0xffffffffu, sum0, 2);
        sum1 += __shfl_xor_sync(0xffffffffu, sum1, 1);
        sum1 += __shfl_xor_sync(0xffffffffu, sum1, 2);
        lrow0 = lrow0 * corr0 + sum0;
        lrow1 = lrow1 * corr1 + sum1;
#pragma unroll
        for (int nt = 0; nt < 8; nt++) {
            oacc[nt][0] *= corr0; oacc[nt][1] *= corr0;
            oacc[nt][2] *= corr1; oacc[nt][3] *= corr1;
        }

        // ---- write P as packed bf16 pairs (cols 2tg,2tg+1), hi/lo ----
#pragma unroll
        for (int nt = 0; nt < 4; nt++) {
            const int kp = nt * 4 + tg;
            float p0 = sacc[nt][0], p1 = sacc[nt][1];
            sPh[(wr + g) * PSTRB + kp] = packbf(p0, p1);
            sPl[(wr + g) * PSTRB + kp] =
                packbf(p0 - bfround(p0), p1 - bfround(p1));
            float p2 = sacc[nt][2], p3 = sacc[nt][3];
            sPh[(wr + g + 8) * PSTRB + kp] = packbf(p2, p3);
            sPl[(wr + g + 8) * PSTRB + kp] =
                packbf(p2 - bfround(p2), p3 - bfround(p3));
        }
        __syncwarp();

        // ---- O += P @ V (warp: 16 rows x 64 cols; 2 ks x 8 nt x 3) ----
#pragma unroll
        for (int ks = 0; ks < 2; ks++) {
            uint32_t pa[4], pl[4];
            pa[0] = sPh[(wr + g) * PSTRB + ks * 8 + tg];
            pa[1] = sPh[(wr + g + 8) * PSTRB + ks * 8 + tg];
            pa[2] = sPh[(wr + g) * PSTRB + ks * 8 + tg + 4];
            pa[3] = sPh[(wr + g + 8) * PSTRB + ks * 8 + tg + 4];
            pl[0] = sPl[(wr + g) * PSTRB + ks * 8 + tg];
            pl[1] = sPl[(wr + g + 8) * PSTRB + ks * 8 + tg];
            pl[2] = sPl[(wr + g) * PSTRB + ks * 8 + tg + 4];
            pl[3] = sPl[(wr + g + 8) * PSTRB + ks * 8 + tg + 4];
#pragma unroll
            for (int nt = 0; nt < 8; nt++) {
                const int n0 = nt * 8 + g;
                uint32_t vh[2], vl[2];
                vh[0] = sVh[(ks * 8 + tg) * VSTRB + n0];
                vh[1] = sVh[(ks * 8 + tg + 4) * VSTRB + n0];
                vl[0] = sVl[(ks * 8 + tg) * VSTRB + n0];
                vl[1] = sVl[(ks * 8 + tg + 4) * VSTRB + n0];
                mma_bf16(oacc[nt], pa, vh);
                mma_bf16(oacc[nt], pa, vl);
                mma_bf16(oacc[nt], pl, vh);
            }
        }
    }

    // ---- epilogue: normalize, write [B,T,H*HD] ----
    const float inv0 = 1.f / lrow0;
    const float inv1 = 1.f / lrow1;
    const size_t ob0 = ((size_t)bb * TT + qrow0) * (HH * HDIM) + h * HDIM;
    const size_t ob1 = ((size_t)bb * TT + qrow1) * (HH * HDIM) + h * HDIM;
#pragma unroll
    for (int nt = 0; nt < 8; nt++) {
        const int c0 = nt * 8 + 2 * tg;
        Og[ob0 + c0]     = oacc[nt][0] * inv0;
        Og[ob0 + c0 + 1] = oacc[nt][1] * inv0;
        Og[ob1 + c0]     = oacc[nt][2] * inv1;
        Og[ob1 + c0 + 1] = oacc[nt][3] * inv1;
    }
}

// ---------------------------------------------------------------------------
extern "C" void kernel_launch(void* const* d_in, const int* in_sizes, int n_in,
                              void* d_out, int out_size) {
    const float* x  = (const float*)d_in[0];
    const float* Wq = (const float*)d_in[1];
    const float* Wk = (const float*)d_in[2];
    const float* Wv = (const float*)d_in[3];
    const float* Wo = (const float*)d_in[4];
    const float* bo = (const float*)d_in[5];
    if (n_in >= 6) {
        const float* big[8]; int nb = 0;
        const float* xx = 0; const float* bb = 0;
        for (int i = 0; i < n_in && i < 8; i++) {
            if (in_sizes[i] == BB * TT * DD)           xx = (const float*)d_in[i];
            else if (in_sizes[i] == DD)                bb = (const float*)d_in[i];
            else if (in_sizes[i] == DD * DD && nb < 8) big[nb++] = (const float*)d_in[i];
        }
        if (xx && bb && nb == 4) {
            x = xx; bo = bb;
            Wq = big[0]; Wk = big[1]; Wv = big[2]; Wo = big[3];
        }
    }
    float* out = (float*)d_out;
    (void)out_size;

    qkv_mma_kernel<<<dim3(MM / 128, NQ / 128, 3), 256>>>(x, Wq, Wk, Wv);
    attn_mma_kernel<<<dim3(BB * HH, TT / 64), 128>>>();
    out_mma_kernel<<<dim3(MM / 128, DD / 128), 256>>>(Wo, bo, out);
}

// round 17
// speedup vs baseline: 2.2059x; 1.0176x over previous
#include <cuda_runtime.h>
#include <cuda_bf16.h>
#include <cstdint>

#define BB   2
#define TT   2048
#define DD   1024
#define HH   16
#define HDIM 64
#define MM   (BB*TT)          // 4096
#define NQ   (HH*HDIM)        // 1024
#define SZ   (BB*HH*TT*HDIM)  // 4,194,304

// One scratch array: [0]=q, [1]=k, [2]=v, [3]=attention output
__device__ __align__(256) float g_scratch[4ull * SZ];

// ======================= mma helpers =======================================
__device__ __forceinline__ void mma_bf16(float* d, const uint32_t* a,
                                         const uint32_t* b) {
    asm volatile(
        "mma.sync.aligned.m16n8k16.row.col.f32.bf16.bf16.f32 "
        "{%0,%1,%2,%3}, {%4,%5,%6,%7}, {%8,%9}, {%0,%1,%2,%3};"
        : "+f"(d[0]), "+f"(d[1]), "+f"(d[2]), "+f"(d[3])
        : "r"(a[0]), "r"(a[1]), "r"(a[2]), "r"(a[3]), "r"(b[0]), "r"(b[1]));
}
__device__ __forceinline__ float bfround(float x) {
    return __bfloat162float(__float2bfloat16_rn(x));
}
__device__ __forceinline__ uint32_t packbf(float a, float b) {
    __nv_bfloat162 t = __floats2bfloat162_rn(a, b);
    return *reinterpret_cast<uint32_t*>(&t);
}

// =================== bf16 GEMM smem layout (R14, proven) ===================
#define ABSTR 12
#define BBSTR 136
struct GemmSmemBF {
    uint32_t Ah[128 * ABSTR];
    uint32_t Al[128 * ABSTR];
    uint32_t Bh[8 * BBSTR];
    uint32_t Bl[8 * BBSTR];
};

__device__ __forceinline__ void mma_chunk_bf(const GemmSmemBF& sm, int wid,
                                             int lane, float acc[4][4][4]) {
    const int warp_m = (wid >> 2) * 64;
    const int warp_n = (wid & 3) * 32;
    const int g  = lane >> 2;
    const int tg = lane & 3;

    uint32_t bh[4][2], bl[4][2];
#pragma unroll
    for (int nt = 0; nt < 4; nt++) {
        const int n0 = warp_n + nt * 8 + g;
        bh[nt][0] = sm.Bh[tg * BBSTR + n0];
        bh[nt][1] = sm.Bh[(tg + 4) * BBSTR + n0];
        bl[nt][0] = sm.Bl[tg * BBSTR + n0];
        bl[nt][1] = sm.Bl[(tg + 4) * BBSTR + n0];
    }
#pragma unroll
    for (int mt = 0; mt < 4; mt++) {
        const int r0 = warp_m + mt * 16 + g;
        uint32_t ah[4], al[4];
        ah[0] = sm.Ah[r0 * ABSTR + tg];
        ah[1] = sm.Ah[(r0 + 8) * ABSTR + tg];
        ah[2] = sm.Ah[r0 * ABSTR + tg + 4];
        ah[3] = sm.Ah[(r0 + 8) * ABSTR + tg + 4];
        al[0] = sm.Al[r0 * ABSTR + tg];
        al[1] = sm.Al[(r0 + 8) * ABSTR + tg];
        al[2] = sm.Al[r0 * ABSTR + tg + 4];
        al[3] = sm.Al[(r0 + 8) * ABSTR + tg + 4];
#pragma unroll
        for (int nt = 0; nt < 4; nt++) {
            mma_bf16(acc[mt][nt], ah, bh[nt]);
            mma_bf16(acc[mt][nt], ah, bl[nt]);
            mma_bf16(acc[mt][nt], al, bh[nt]);
        }
    }
}

__device__ __forceinline__ void store_a_bf(GemmSmemBF& sm, int row, int c4,
                                           float4 av) {
    const int kp = c4 >> 1;
    uint32_t h0 = packbf(av.x, av.y);
    uint32_t h1 = packbf(av.z, av.w);
    uint32_t l0 = packbf(av.x - bfround(av.x), av.y - bfround(av.y));
    uint32_t l1 = packbf(av.z - bfround(av.z), av.w - bfround(av.w));
    *reinterpret_cast<uint2*>(&sm.Ah[row * ABSTR + kp]) = make_uint2(h0, h1);
    *reinterpret_cast<uint2*>(&sm.Al[row * ABSTR + kp]) = make_uint2(l0, l1);
}
__device__ __forceinline__ void store_b_bf(GemmSmemBF& sm, int kp, int n4,
                                           float4 b0, float4 b1) {
    const float x0[4] = {b0.x, b0.y, b0.z, b0.w};
    const float x1[4] = {b1.x, b1.y, b1.z, b1.w};
    uint32_t wh[4], wl[4];
#pragma unroll
    for (int j = 0; j < 4; j++) {
        wh[j] = packbf(x0[j], x1[j]);
        wl[j] = packbf(x0[j] - bfround(x0[j]), x1[j] - bfround(x1[j]));
    }
    *reinterpret_cast<uint4*>(&sm.Bh[kp * BBSTR + n4]) =
        make_uint4(wh[0], wh[1], wh[2], wh[3]);
    *reinterpret_cast<uint4*>(&sm.Bl[kp * BBSTR + n4]) =
        make_uint4(wl[0], wl[1], wl[2], wl[3]);
}

// ---------------------------------------------------------------------------
// QKV projection (bf16 tensor, double-buffered). Grid (32, 8, 3), block 256.
// ---------------------------------------------------------------------------
__global__ __launch_bounds__(256, 2)
void qkv_mma_kernel(const float* __restrict__ x,
                    const float* __restrict__ Wq,
                    const float* __restrict__ Wk,
                    const float* __restrict__ Wv) {
    __shared__ GemmSmemBF sm[2];
    const float* W = (blockIdx.z == 0) ? Wq : (blockIdx.z == 1) ? Wk : Wv;
    float* out = g_scratch + (size_t)blockIdx.z * SZ;

    const int bm   = blockIdx.x * 128;
    const int bn   = blockIdx.y * 128;
    const int tid  = threadIdx.x;
    const int wid  = tid >> 5;
    const int lane = tid & 31;

    // loop-invariant load geometry
    int arow[2], ac4[2];
#pragma unroll
    for (int it = 0; it < 2; it++) {
        int idx = tid + it * 256;
        arow[it] = idx >> 2;
        ac4[it]  = (idx & 3) << 2;
    }
    const int bn4   = (tid & 31) << 2;
    const int bkp   = tid >> 5;
    const int nglob = bn + bn4;
    const size_t bcol = ((size_t)(nglob >> 6) * DD) * HDIM + (nglob & 63);

    float acc[4][4][4];
#pragma unroll
    for (int mt = 0; mt < 4; mt++)
#pragma unroll
        for (int nt = 0; nt < 4; nt++)
#pragma unroll
            for (int r = 0; r < 4; r++) acc[mt][nt][r] = 0.f;

    float4 av[2], bv0, bv1;
    // ---- prologue: chunk 0 ----
#pragma unroll
    for (int it = 0; it < 2; it++)
        av[it] = *reinterpret_cast<const float4*>(
            &x[(size_t)(bm + arow[it]) * DD + ac4[it]]);
    {
        const int d0 = bkp * 2;
        bv0 = *reinterpret_cast<const float4*>(&W[bcol + (size_t)d0 * HDIM]);
        bv1 = *reinterpret_cast<const float4*>(&W[bcol + (size_t)(d0 + 1) * HDIM]);
    }
#pragma unroll
    for (int it = 0; it < 2; it++) store_a_bf(sm[0], arow[it], ac4[it], av[it]);
    store_b_bf(sm[0], bkp, bn4, bv0, bv1);
    __syncthreads();

    for (int c = 0; c < 64; c++) {
        const int cur = c & 1, nxt = cur ^ 1;
        if (c < 63) {
            const int k0 = (c + 1) * 16;
#pragma unroll
            for (int it = 0; it < 2; it++)
                av[it] = *reinterpret_cast<const float4*>(
                    &x[(size_t)(bm + arow[it]) * DD + k0 + ac4[it]]);
            const int d0 = k0 + bkp * 2;
            bv0 = *reinterpret_cast<const float4*>(&W[bcol + (size_t)d0 * HDIM]);
            bv1 = *reinterpret_cast<const float4*>(&W[bcol + (size_t)(d0 + 1) * HDIM]);
        }
        mma_chunk_bf(sm[cur], wid, lane, acc);
        if (c < 63) {
#pragma unroll
            for (int it = 0; it < 2; it++)
                store_a_bf(sm[nxt], arow[it], ac4[it], av[it]);
            store_b_bf(sm[nxt], bkp, bn4, bv0, bv1);
        }
        __syncthreads();
    }

    const int warp_m = (wid >> 2) * 64;
    const int warp_n = (wid & 3) * 32;
    const int g  = lane >> 2;
    const int tg = lane & 3;
#pragma unroll
    for (int mt = 0; mt < 4; mt++) {
#pragma unroll
        for (int nt = 0; nt < 4; nt++) {
#pragma unroll
            for (int r = 0; r < 4; r++) {
                int m = bm + warp_m + mt * 16 + g + ((r >= 2) ? 8 : 0);
                int n = bn + warp_n + nt * 8 + tg * 2 + (r & 1);
                int b = m >> 11, t = m & 2047;
                out[(((size_t)b * HH + (n >> 6)) * TT + t) * HDIM + (n & 63)] =
                    acc[mt][nt][r];
            }
        }
    }
}

// ---------------------------------------------------------------------------
// Output projection (bf16 tensor, double-buffered). Grid (32, 8), block 256.
// ---------------------------------------------------------------------------
__global__ __launch_bounds__(256, 2)
void out_mma_kernel(const float* __restrict__ Wo,
                    const float* __restrict__ bo,
                    float* __restrict__ outp) {
    __shared__ GemmSmemBF sm[2];
    const float* A = g_scratch + 3ull * SZ;

    const int bm   = blockIdx.x * 128;
    const int bn   = blockIdx.y * 128;
    const int tid  = threadIdx.x;
    const int wid  = tid >> 5;
    const int lane = tid & 31;

    int arow[2], ac4[2];
#pragma unroll
    for (int it = 0; it < 2; it++) {
        int idx = tid + it * 256;
        arow[it] = idx >> 2;
        ac4[it]  = (idx & 3) << 2;
    }
    const int bn4 = (tid & 31) << 2;
    const int bkp = tid >> 5;

    float acc[4][4][4];
#pragma unroll
    for (int mt = 0; mt < 4; mt++)
#pragma unroll
        for (int nt = 0; nt < 4; nt++)
#pragma unroll
            for (int r = 0; r < 4; r++) acc[mt][nt][r] = 0.f;

    float4 av[2], bv0, bv1;
#pragma unroll
    for (int it = 0; it < 2; it++)
        av[it] = *reinterpret_cast<const float4*>(
            &A[(size_t)(bm + arow[it]) * DD + ac4[it]]);
    {
        const int d0 = bkp * 2;
        bv0 = *reinterpret_cast<const float4*>(&Wo[(size_t)d0 * DD + bn + bn4]);
        bv1 = *reinterpret_cast<const float4*>(&Wo[(size_t)(d0 + 1) * DD + bn + bn4]);
    }
#pragma unroll
    for (int it = 0; it < 2; it++) store_a_bf(sm[0], arow[it], ac4[it], av[it]);
    store_b_bf(sm[0], bkp, bn4, bv0, bv1);
    __syncthreads();

    for (int c = 0; c < 64; c++) {
        const int cur = c & 1, nxt = cur ^ 1;
        if (c < 63) {
            const int k0 = (c + 1) * 16;
#pragma unroll
            for (int it = 0; it < 2; it++)
                av[it] = *reinterpret_cast<const float4*>(
                    &A[(size_t)(bm + arow[it]) * DD + k0 + ac4[it]]);
            const int d0 = k0 + bkp * 2;
            bv0 = *reinterpret_cast<const float4*>(&Wo[(size_t)d0 * DD + bn + bn4]);
            bv1 = *reinterpret_cast<const float4*>(&Wo[(size_t)(d0 + 1) * DD + bn + bn4]);
        }
        mma_chunk_bf(sm[cur], wid, lane, acc);
        if (c < 63) {
#pragma unroll
            for (int it = 0; it < 2; it++)
                store_a_bf(sm[nxt], arow[it], ac4[it], av[it]);
            store_b_bf(sm[nxt], bkp, bn4, bv0, bv1);
        }
        __syncthreads();
    }

    const int warp_m = (wid >> 2) * 64;
    const int warp_n = (wid & 3) * 32;
    const int g  = lane >> 2;
    const int tg = lane & 3;
#pragma unroll
    for (int mt = 0; mt < 4; mt++) {
#pragma unroll
        for (int nt = 0; nt < 4; nt++) {
#pragma unroll
            for (int r = 0; r < 4; r++) {
                int m = bm + warp_m + mt * 16 + g + ((r >= 2) ? 8 : 0);
                int n = bn + warp_n + nt * 8 + tg * 2 + (r & 1);
                outp[(size_t)m * DD + n] = acc[mt][nt][r] + bo[n];
            }
        }
    }
}

// ---------------------------------------------------------------------------
// bf16 tensor-core flash attention (causal, double-buffered K/V).
// Grid: (B*H, T/64). Block: 128 threads = 4 warps; warp owns 16 query rows.
// ---------------------------------------------------------------------------
#define KSTRB 36
#define VSTRB 72
#define PSTRB 20

__global__ __launch_bounds__(128)
void attn_mma_kernel() {
    __shared__ uint32_t sKh[2][32 * KSTRB], sKl[2][32 * KSTRB];
    __shared__ uint32_t sVh[2][16 * VSTRB], sVl[2][16 * VSTRB];
    __shared__ uint32_t sPh[64 * PSTRB], sPl[64 * PSTRB];

    const int bh = blockIdx.x;
    const int qt = blockIdx.y;
    const int bb = bh >> 4;
    const int h  = bh & 15;
    const size_t base = (size_t)bh * TT * HDIM;
    const float* Qg = g_scratch + 0ull * SZ + base;
    const float* Kg = g_scratch + 1ull * SZ + base;
    const float* Vg = g_scratch + 2ull * SZ + base;
    float*       Og = g_scratch + 3ull * SZ;

    const int tid  = threadIdx.x;
    const int wid  = tid >> 5;
    const int lane = tid & 31;
    const int g    = lane >> 2;
    const int tg   = lane & 3;
    const int wr   = wid * 16;
    const int qrow0 = qt * 64 + wr + g;
    const int qrow1 = qrow0 + 8;

    // loop-invariant K/V load geometry
    int krow[4], kc4[4];
#pragma unroll
    for (int it = 0; it < 4; it++) {
        int idx = tid + it * 128;
        krow[it] = idx >> 4;
        kc4[it]  = (idx & 15) << 2;
    }
    int vkp[2], vn4[2];
#pragma unroll
    for (int it = 0; it < 2; it++) {
        int idx = tid + it * 128;
        vkp[it] = idx >> 4;
        vn4[it] = (idx & 15) << 2;
    }

    float4 kreg[4], vreg[4];
    auto load_kv = [&](int kt) {
#pragma unroll
        for (int it = 0; it < 4; it++)
            kreg[it] = *reinterpret_cast<const float4*>(
                &Kg[(size_t)(kt * 32 + krow[it]) * HDIM + kc4[it]]);
#pragma unroll
        for (int it = 0; it < 2; it++) {
            const int d0 = kt * 32 + vkp[it] * 2;
            vreg[2 * it]     = *reinterpret_cast<const float4*>(
                &Vg[(size_t)d0 * HDIM + vn4[it]]);
            vreg[2 * it + 1] = *reinterpret_cast<const float4*>(
                &Vg[(size_t)(d0 + 1) * HDIM + vn4[it]]);
        }
    };
    auto store_kv = [&](int b) {
#pragma unroll
        for (int it = 0; it < 4; it++) {
            float4 kv = kreg[it];
            uint32_t h0 = packbf(kv.x, kv.y);
            uint32_t h1 = packbf(kv.z, kv.w);
            uint32_t l0 = packbf(kv.x - bfround(kv.x), kv.y - bfround(kv.y));
            uint32_t l1 = packbf(kv.z - bfround(kv.z), kv.w - bfround(kv.w));
            *reinterpret_cast<uint2*>(&sKh[b][krow[it] * KSTRB + (kc4[it] >> 1)]) =
                make_uint2(h0, h1);
            *reinterpret_cast<uint2*>(&sKl[b][krow[it] * KSTRB + (kc4[it] >> 1)]) =
                make_uint2(l0, l1);
        }
#pragma unroll
        for (int it = 0; it < 2; it++) {
            float4 v0 = vreg[2 * it], v1 = vreg[2 * it + 1];
            const float x0[4] = {v0.x, v0.y, v0.z, v0.w};
            const float x1[4] = {v1.x, v1.y, v1.z, v1.w};
            uint32_t wh[4], wl[4];
#pragma unroll
            for (int j = 0; j < 4; j++) {
                wh[j] = packbf(x0[j], x1[j]);
                wl[j] = packbf(x0[j] - bfround(x0[j]), x1[j] - bfround(x1[j]));
            }
            *reinterpret_cast<uint4*>(&sVh[b][vkp[it] * VSTRB + vn4[it]]) =
                make_uint4(wh[0], wh[1], wh[2], wh[3]);
            *reinterpret_cast<uint4*>(&sVl[b][vkp[it] * VSTRB + vn4[it]]) =
                make_uint4(wl[0], wl[1], wl[2], wl[3]);
        }
    };

    // ---- Q fragments (packed bf16 pairs, hi/lo) ----
    uint32_t qh[4][4], ql[4][4];
#pragma unroll
    for (int ks = 0; ks < 4; ks++) {
#pragma unroll
        for (int r = 0; r < 4; r++) {
            int row = (r & 1) ? qrow1 : qrow0;
            int col = ks * 16 + ((r >= 2) ? 8 : 0) + 2 * tg;
            float2 v = *reinterpret_cast<const float2*>(
                &Qg[(size_t)row * HDIM + col]);
            qh[ks][r] = packbf(v.x, v.y);
            ql[ks][r] = packbf(v.x - bfround(v.x), v.y - bfround(v.y));
        }
    }

    float oacc[8][4];
#pragma unroll
    for (int nt = 0; nt < 8; nt++)
#pragma unroll
        for (int r = 0; r < 4; r++) oacc[nt][r] = 0.f;
    float mrow0 = -1e30f, mrow1 = -1e30f, lrow0 = 0.f, lrow1 = 0.f;
    const float scale = 0.125f;

    const int kt_max = 2 * qt + 1;

    // prologue: tile 0 into buffer 0
    load_kv(0);
    store_kv(0);
    __syncthreads();

    for (int kt = 0; kt <= kt_max; kt++) {
        const int cur = kt & 1;
        if (kt < kt_max) load_kv(kt + 1);

        // ---- S = Q K^T ----
        float sacc[4][4];
#pragma unroll
        for (int nt = 0; nt < 4; nt++)
#pragma unroll
            for (int r = 0; r < 4; r++) sacc[nt][r] = 0.f;
#pragma unroll
        for (int ks = 0; ks < 4; ks++) {
#pragma unroll
            for (int nt = 0; nt < 4; nt++) {
                const int n0 = nt * 8 + g;
                uint32_t bhf[2], blf[2];
                bhf[0] = sKh[cur][n0 * KSTRB + ks * 8 + tg];
                bhf[1] = sKh[cur][n0 * KSTRB + ks * 8 + tg + 4];
                blf[0] = sKl[cur][n0 * KSTRB + ks * 8 + tg];
                blf[1] = sKl[cur][n0 * KSTRB + ks * 8 + tg + 4];
                mma_bf16(sacc[nt], qh[ks], bhf);
                mma_bf16(sacc[nt], qh[ks], blf);
                mma_bf16(sacc[nt], ql[ks], bhf);
            }
        }

        // ---- scale + causal mask + online softmax ----
        float mt0 = -1e30f, mt1 = -1e30f;
#pragma unroll
        for (int nt = 0; nt < 4; nt++) {
#pragma unroll
            for (int j = 0; j < 2; j++) {
                int scol = kt * 32 + nt * 8 + 2 * tg + j;
                float sv0 = sacc[nt][j] * scale;
                if (scol > qrow0) sv0 = -1e30f;
                sacc[nt][j] = sv0;
                mt0 = fmaxf(mt0, sv0);
                float sv1 = sacc[nt][2 + j] * scale;
                if (scol > qrow1) sv1 = -1e30f;
                sacc[nt][2 + j] = sv1;
                mt1 = fmaxf(mt1, sv1);
            }
        }
        mt0 = fmaxf(mt0, __shfl_xor_sync(0xffffffffu, mt0, 1));
        mt0 = fmaxf(mt0, __shfl_xor_sync(0xffffffffu, mt0, 2));
        mt1 = fmaxf(mt1, __shfl_xor_sync(0xffffffffu, mt1, 1));
        mt1 = fmaxf(mt1, __shfl_xor_sync(0xffffffffu, mt1, 2));

        float mn0 = fmaxf(mrow0, mt0), mn1 = fmaxf(mrow1, mt1);
        float corr0 = __expf(mrow0 - mn0), corr1 = __expf(mrow1 - mn1);
        mrow0 = mn0; mrow1 = mn1;
        float sum0 = 0.f, sum1 = 0.f;
#pragma unroll
        for (int nt = 0; nt < 4; nt++) {
#pragma unroll
            for (int j = 0; j < 2; j++) {
                float p0 = __expf(sacc[nt][j] - mn0);
                sacc[nt][j] = p0; sum0 += p0;
                float p1 = __expf(sacc[nt][2 + j] - mn1);
                sacc[nt][2 + j] = p1; sum1 += p1;
            }
        }
        sum0 += __shfl_xor_sync(0xffffffffu, sum0, 1);
        sum0 += __shfl_xor_sync(0xffffffffu, sum0, 2);
        sum1 += __shfl_xor_sync(0xffffffffu, sum1, 1);
        sum1 += __shfl_xor_sync(0xffffffffu, sum1, 2);
        lrow0 = lrow0 * corr0 + sum0;
        lrow1 = lrow1 * corr1 + sum1;
#pragma unroll
        for (int nt = 0; nt < 8; nt++) {
            oacc[nt][0] *= corr0; oacc[nt][1] *= corr0;
            oacc[nt][2] *= corr1; oacc[nt][3] *= corr1;
        }

        // ---- write P (warp-private rows) ----
#pragma unroll
        for (int nt = 0; nt < 4; nt++) {
            const int kp = nt * 4 + tg;
            float p0 = sacc[nt][0], p1 = sacc[nt][1];
            sPh[(wr + g) * PSTRB + kp] = packbf(p0, p1);
            sPl[(wr + g) * PSTRB + kp] =
                packbf(p0 - bfround(p0), p1 - bfround(p1));
            float p2 = sacc[nt][2], p3 = sacc[nt][3];
            sPh[(wr + g + 8) * PSTRB + kp] = packbf(p2, p3);
            sPl[(wr + g + 8) * PSTRB + kp] =
                packbf(p2 - bfround(p2), p3 - bfround(p3));
        }
        __syncwarp();

        // ---- O += P @ V ----
#pragma unroll
        for (int ks = 0; ks < 2; ks++) {
            uint32_t pa[4], pl[4];
            pa[0] = sPh[(wr + g) * PSTRB + ks * 8 + tg];
            pa[1] = sPh[(wr + g + 8) * PSTRB + ks * 8 + tg];
            pa[2] = sPh[(wr + g) * PSTRB + ks * 8 + tg + 4];
            pa[3] = sPh[(wr + g + 8) * PSTRB + ks * 8 + tg + 4];
            pl[0] = sPl[(wr + g) * PSTRB + ks * 8 + tg];
            pl[1] = sPl[(wr + g + 8) * PSTRB + ks * 8 + tg];
            pl[2] = sPl[(wr + g) * PSTRB + ks * 8 + tg + 4];
            pl[3] = sPl[(wr + g + 8) * PSTRB + ks * 8 + tg + 4];
#pragma unroll
            for (int nt = 0; nt < 8; nt++) {
                const int n0 = nt * 8 + g;
                uint32_t vh[2], vl[2];
                vh[0] = sVh[cur][(ks * 8 + tg) * VSTRB + n0];
                vh[1] = sVh[cur][(ks * 8 + tg + 4) * VSTRB + n0];
                vl[0] = sVl[cur][(ks * 8 + tg) * VSTRB + n0];
                vl[1] = sVl[cur][(ks * 8 + tg + 4) * VSTRB + n0];
                mma_bf16(oacc[nt], pa, vh);
                mma_bf16(oacc[nt], pa, vl);
                mma_bf16(oacc[nt], pl, vh);
            }
        }

        if (kt < kt_max) store_kv(cur ^ 1);
        __syncthreads();
    }

    // ---- epilogue: normalize, write [B,T,H*HD] ----
    const float inv0 = 1.f / lrow0;
    const float inv1 = 1.f / lrow1;
    const size_t ob0 = ((size_t)bb * TT + qrow0) * (HH * HDIM) + h * HDIM;
    const size_t ob1 = ((size_t)bb * TT + qrow1) * (HH * HDIM) + h * HDIM;
#pragma unroll
    for (int nt = 0; nt < 8; nt++) {
        const int c0 = nt * 8 + 2 * tg;
        Og[ob0 + c0]     = oacc[nt][0] * inv0;
        Og[ob0 + c0 + 1] = oacc[nt][1] * inv0;
        Og[ob1 + c0]     = oacc[nt][2] * inv1;
        Og[ob1 + c0 + 1] = oacc[nt][3] * inv1;
    }
}

// ---------------------------------------------------------------------------
extern "C" void kernel_launch(void* const* d_in, const int* in_sizes, int n_in,
                              void* d_out, int out_size) {
    const float* x  = (const float*)d_in[0];
    const float* Wq = (const float*)d_in[1];
    const float* Wk = (const float*)d_in[2];
    const float* Wv = (const float*)d_in[3];
    const float* Wo = (const float*)d_in[4];
    const float* bo = (const float*)d_in[5];
    if (n_in >= 6) {
        const float* big[8]; int nb = 0;
        const float* xx = 0; const float* bb = 0;
        for (int i = 0; i < n_in && i < 8; i++) {
            if (in_sizes[i] == BB * TT * DD)           xx = (const float*)d_in[i];
            else if (in_sizes[i] == DD)                bb = (const float*)d_in[i];
            else if (in_sizes[i] == DD * DD && nb < 8) big[nb++] = (const float*)d_in[i];
        }
        if (xx && bb && nb == 4) {
            x = xx; bo = bb;
            Wq = big[0]; Wk = big[1]; Wv = big[2]; Wo = big[3];
        }
    }
    float* out = (float*)d_out;
    (void)out_size;

    qkv_mma_kernel<<<dim3(MM / 128, NQ / 128, 3), 256>>>(x, Wq, Wk, Wv);
    attn_mma_kernel<<<dim3(BB * HH, TT / 64), 128>>>();
    out_mma_kernel<<<dim3(MM / 128, DD / 128), 256>>>(Wo, bo, out);
}